// round 1
// baseline (speedup 1.0000x reference)
#include <cuda_runtime.h>
#include <cuda_bf16.h>
#include <math.h>

// Problem constants
#define H  512
#define E  321
#define CC 321
#define T  96
#define P  96
#define B  512
#define G4 (4 * H)   // 2048

// ---------------- scratch (device globals; no allocation allowed) ----------
__device__ float g_xT[(size_t)T * B * E];        // x_enc transposed to (T,B,E)
__device__ float g_pre[(size_t)T * B * G4];      // precomputed x@Wih^T for all steps
__device__ float g_ys[(size_t)T * B * H];        // encoder layer0 outputs (T,B,H)
__device__ float g_hc[4 * B * H];                // h0,c0,h1,c1
__device__ float g_gates[B * G4];                // per-step gate scratch
__device__ float g_inp[B * E];                   // decoder initial input

// ---------------- GEMM: C[m,n] = sum A1[m,:]*W1[n,:] (+ A2*W2) (+ bias) -----
#define BM 64
#define BN 64
#define BK 16

__global__ __launch_bounds__(256)
void gemm2_kernel(float* __restrict__ C, int ldc,
                  const float* __restrict__ A1, int lda1, int K1,
                  const float* __restrict__ W1,
                  const float* __restrict__ A2, int lda2, int K2,
                  const float* __restrict__ W2,
                  const float* __restrict__ bias,
                  int M, int N)
{
    __shared__ float As[BK][BM];
    __shared__ float Ws[BK][BN];

    const int bm = blockIdx.y * BM;
    const int bn = blockIdx.x * BN;
    const int tid = threadIdx.x;       // 0..255
    const int tr = tid >> 4;           // 0..15 (row group)
    const int tc = tid & 15;           // 0..15 (col group)

    float acc[4][4];
#pragma unroll
    for (int i = 0; i < 4; ++i)
#pragma unroll
        for (int j = 0; j < 4; ++j) acc[i][j] = 0.f;

    for (int phase = 0; phase < 2; ++phase) {
        const float* A  = phase ? A2 : A1;
        const float* W  = phase ? W2 : W1;
        const int K     = phase ? K2 : K1;
        const int lda   = phase ? lda2 : lda1;
        if (A == nullptr) continue;

        for (int k0 = 0; k0 < K; k0 += BK) {
            // Load A tile (BM x BK), 4 elems per thread, k-contiguous
#pragma unroll
            for (int i = 0; i < 4; ++i) {
                int l = tid * 4 + i;           // 0..1023
                int m = l >> 4;
                int k = l & 15;
                int gm = bm + m, gk = k0 + k;
                float v = 0.f;
                if (gm < M && gk < K) v = A[(size_t)gm * lda + gk];
                As[k][m] = v;
            }
            // Load W tile (BN x BK): W is row-major (N x K)
#pragma unroll
            for (int i = 0; i < 4; ++i) {
                int l = tid * 4 + i;
                int n = l >> 4;
                int k = l & 15;
                int gn = bn + n, gk = k0 + k;
                float v = 0.f;
                if (gn < N && gk < K) v = W[(size_t)gn * K + gk];
                Ws[k][n] = v;
            }
            __syncthreads();

#pragma unroll
            for (int kk = 0; kk < BK; ++kk) {
                float4 a = *(const float4*)&As[kk][tr * 4];
                float4 w = *(const float4*)&Ws[kk][tc * 4];
                float av[4] = {a.x, a.y, a.z, a.w};
                float wv[4] = {w.x, w.y, w.z, w.w};
#pragma unroll
                for (int i = 0; i < 4; ++i)
#pragma unroll
                    for (int j = 0; j < 4; ++j)
                        acc[i][j] += av[i] * wv[j];
            }
            __syncthreads();
        }
    }

#pragma unroll
    for (int i = 0; i < 4; ++i) {
        int gm = bm + tr * 4 + i;
        if (gm >= M) continue;
#pragma unroll
        for (int j = 0; j < 4; ++j) {
            int gn = bn + tc * 4 + j;
            if (gn < N) {
                float v = acc[i][j];
                if (bias) v += bias[gn];
                C[(size_t)gm * ldc + gn] = v;
            }
        }
    }
}

// ---------------- LSTM gate / elementwise step ------------------------------
__device__ __forceinline__ float sigm(float x) { return 1.f / (1.f + __expf(-x)); }

__global__ void lstm_gate_kernel(const float* __restrict__ gemmout,  // B x 4H
                                 const float* __restrict__ pre,      // B x 4H or null
                                 const float* __restrict__ bih,
                                 const float* __restrict__ bhh,
                                 float* __restrict__ h,              // B x H
                                 float* __restrict__ c,              // B x H
                                 float* __restrict__ ys)             // B x H or null
{
    int idx = blockIdx.x * blockDim.x + threadIdx.x;
    if (idx >= B * H) return;
    int b = idx / H, j = idx % H;
    size_t base = (size_t)b * G4;

    float gi = gemmout[base + j]         + bih[j]         + bhh[j];
    float gf = gemmout[base + H + j]     + bih[H + j]     + bhh[H + j];
    float gg = gemmout[base + 2 * H + j] + bih[2 * H + j] + bhh[2 * H + j];
    float go = gemmout[base + 3 * H + j] + bih[3 * H + j] + bhh[3 * H + j];
    if (pre) {
        gi += pre[base + j];
        gf += pre[base + H + j];
        gg += pre[base + 2 * H + j];
        go += pre[base + 3 * H + j];
    }
    float cv = sigm(gf) * c[idx] + sigm(gi) * tanhf(gg);
    float hv = sigm(go) * tanhf(cv);
    c[idx] = cv;
    h[idx] = hv;
    if (ys) ys[idx] = hv;
}

// ---------------- small helper kernels --------------------------------------
__global__ void zero_kernel(float* p, int n) {
    int i = blockIdx.x * blockDim.x + threadIdx.x;
    if (i < n) p[i] = 0.f;
}

// (B,T,E) -> (T,B,E)
__global__ void transpose_bt_kernel(const float* __restrict__ in, float* __restrict__ out) {
    size_t i = (size_t)blockIdx.x * blockDim.x + threadIdx.x;
    size_t total = (size_t)B * T * E;
    if (i >= total) return;
    size_t e = i % E;
    size_t t = (i / E) % T;
    size_t b = i / ((size_t)E * T);
    out[(t * B + b) * E + e] = in[i];
}

// g_inp[b,:] = x_enc[b, T-1, :]
__global__ void copy_last_kernel(const float* __restrict__ x, float* __restrict__ out) {
    int i = blockIdx.x * blockDim.x + threadIdx.x;
    if (i >= B * E) return;
    int b = i / E, e = i % E;
    out[i] = x[(size_t)b * T * E + (size_t)(T - 1) * E + e];
}

// ---------------- launcher ---------------------------------------------------
static inline void launch_gemm2(float* Cp, int ldc,
                                const float* A1, int lda1, int K1, const float* W1,
                                const float* A2, int lda2, int K2, const float* W2,
                                const float* bias, int M, int N)
{
    dim3 grid((N + BN - 1) / BN, (M + BM - 1) / BM);
    gemm2_kernel<<<grid, 256>>>(Cp, ldc, A1, lda1, K1, W1, A2, lda2, K2, W2, bias, M, N);
}

extern "C" void kernel_launch(void* const* d_in, const int* in_sizes, int n_in,
                              void* d_out, int out_size)
{
    const float* x_enc  = (const float*)d_in[0];
    const float* e_Wih0 = (const float*)d_in[4];
    const float* e_Whh0 = (const float*)d_in[5];
    const float* e_bih0 = (const float*)d_in[6];
    const float* e_bhh0 = (const float*)d_in[7];
    const float* e_Wih1 = (const float*)d_in[8];
    const float* e_Whh1 = (const float*)d_in[9];
    const float* e_bih1 = (const float*)d_in[10];
    const float* e_bhh1 = (const float*)d_in[11];
    const float* d_Wih0 = (const float*)d_in[12];
    const float* d_Whh0 = (const float*)d_in[13];
    const float* d_bih0 = (const float*)d_in[14];
    const float* d_bhh0 = (const float*)d_in[15];
    const float* d_Wih1 = (const float*)d_in[16];
    const float* d_Whh1 = (const float*)d_in[17];
    const float* d_bih1 = (const float*)d_in[18];
    const float* d_bhh1 = (const float*)d_in[19];
    const float* fc_W   = (const float*)d_in[20];
    const float* fc_b   = (const float*)d_in[21];
    float* out = (float*)d_out;

    float *xT, *pre, *ys, *hc, *gates, *inp0;
    cudaGetSymbolAddress((void**)&xT,    g_xT);
    cudaGetSymbolAddress((void**)&pre,   g_pre);
    cudaGetSymbolAddress((void**)&ys,    g_ys);
    cudaGetSymbolAddress((void**)&hc,    g_hc);
    cudaGetSymbolAddress((void**)&gates, g_gates);
    cudaGetSymbolAddress((void**)&inp0,  g_inp);

    float* h0 = hc;
    float* c0 = hc + (size_t)B * H;
    float* h1 = hc + (size_t)2 * B * H;
    float* c1 = hc + (size_t)3 * B * H;

    // 1. zero states
    {
        int n = 4 * B * H;
        zero_kernel<<<(n + 255) / 256, 256>>>(hc, n);
    }

    // 2. transpose x_enc to (T,B,E)
    {
        size_t total = (size_t)B * T * E;
        transpose_bt_kernel<<<(unsigned)((total + 255) / 256), 256>>>(x_enc, xT);
    }

    // 3. encoder layer0 input GEMM for all steps: pre = xT @ e_Wih0^T
    launch_gemm2(pre, G4, xT, E, E, e_Wih0, nullptr, 0, 0, nullptr, nullptr, T * B, G4);

    // 4. encoder layer0 recurrence
    for (int t = 0; t < T; ++t) {
        launch_gemm2(gates, G4, h0, H, H, e_Whh0, nullptr, 0, 0, nullptr, nullptr, B, G4);
        lstm_gate_kernel<<<(B * H + 255) / 256, 256>>>(
            gates, pre + (size_t)t * B * G4, e_bih0, e_bhh0, h0, c0,
            ys + (size_t)t * B * H);
    }

    // 5. encoder layer1 input GEMM: pre = ys @ e_Wih1^T
    launch_gemm2(pre, G4, ys, H, H, e_Wih1, nullptr, 0, 0, nullptr, nullptr, T * B, G4);

    // 6. encoder layer1 recurrence
    for (int t = 0; t < T; ++t) {
        launch_gemm2(gates, G4, h1, H, H, e_Whh1, nullptr, 0, 0, nullptr, nullptr, B, G4);
        lstm_gate_kernel<<<(B * H + 255) / 256, 256>>>(
            gates, pre + (size_t)t * B * G4, e_bih1, e_bhh1, h1, c1, nullptr);
    }

    // 7. decoder initial input = x_enc[:, T-1, :]
    copy_last_kernel<<<(B * E + 255) / 256, 256>>>(x_enc, inp0);

    // 8. decoder autoregressive loop
    for (int t = 0; t < P; ++t) {
        const float* inp = (t == 0) ? inp0 : (out + (size_t)(t - 1) * CC);
        int lda_inp = (t == 0) ? E : (P * CC);

        // cell0: gates = inp @ d_Wih0^T + h0 @ d_Whh0^T
        launch_gemm2(gates, G4, inp, lda_inp, E, d_Wih0, h0, H, H, d_Whh0,
                     nullptr, B, G4);
        lstm_gate_kernel<<<(B * H + 255) / 256, 256>>>(
            gates, nullptr, d_bih0, d_bhh0, h0, c0, nullptr);

        // cell1: gates = h0 @ d_Wih1^T + h1 @ d_Whh1^T
        launch_gemm2(gates, G4, h0, H, H, d_Wih1, h1, H, H, d_Whh1,
                     nullptr, B, G4);
        lstm_gate_kernel<<<(B * H + 255) / 256, 256>>>(
            gates, nullptr, d_bih1, d_bhh1, h1, c1, nullptr);

        // out[:, t, :] = h1 @ fc_W^T + fc_b
        launch_gemm2(out + (size_t)t * CC, P * CC, h1, H, H, fc_W,
                     nullptr, 0, 0, nullptr, fc_b, B, CC);
    }
}